// round 2
// baseline (speedup 1.0000x reference)
#include <cuda_runtime.h>
#include <cstdint>

#define N_ 100000
#define E_ 3200000
#define D_ 64
#define NCAND 1024
#define CAP 4096

// ---------------- device scratch (static, no runtime allocation) ----------------
__device__ float4 g_fst [N_*16];
__device__ float4 g_emb1[N_*16];
__device__ float4 g_emb2[N_*16];
__device__ float  g_v1[E_];
__device__ float  g_v2[E_];
__device__ float  g_order0[N_];
__device__ float  g_order1[N_];
__device__ float  g_num1[N_];
__device__ float  g_num2[N_];
__device__ unsigned g_keys[N_];
__device__ unsigned g_hist[256];
__device__ unsigned g_prefix;
__device__ int g_rem;
__device__ int g_selcount;
__device__ unsigned long long g_cand[CAP];

// ---------------- Threefry-2x32 (20 rounds, 5 key injections) -------------------
#define TFR(a,b,r) { a += b; b = ((b << (r)) | (b >> (32-(r)))); b ^= a; }

__host__ __device__ __forceinline__ void tf2x32(unsigned k0, unsigned k1,
                                                unsigned& x0, unsigned& x1) {
    unsigned k2 = k0 ^ k1 ^ 0x1BD11BDAu;
    x0 += k0; x1 += k1;
    TFR(x0,x1,13) TFR(x0,x1,15) TFR(x0,x1,26) TFR(x0,x1,6)
    x0 += k1; x1 += k2 + 1u;
    TFR(x0,x1,17) TFR(x0,x1,29) TFR(x0,x1,16) TFR(x0,x1,24)
    x0 += k2; x1 += k0 + 2u;
    TFR(x0,x1,13) TFR(x0,x1,15) TFR(x0,x1,26) TFR(x0,x1,6)
    x0 += k0; x1 += k1 + 3u;
    TFR(x0,x1,17) TFR(x0,x1,29) TFR(x0,x1,16) TFR(x0,x1,24)
    x0 += k1; x1 += k2 + 4u;
    TFR(x0,x1,13) TFR(x0,x1,15) TFR(x0,x1,26) TFR(x0,x1,6)
    x0 += k2; x1 += k0 + 5u;
}

// Partitionable-mode split: split(key, 2)[j] = threefry(key, (0, j)), new key =
// (x0_out, x1_out).  key, sub = split(key)  -> key = j=0, sub = j=1.
static void jax_split_part(unsigned k0, unsigned k1, unsigned* nk, unsigned* sk) {
    unsigned a0 = 0u, a1 = 0u; tf2x32(k0, k1, a0, a1);   // counter 0
    unsigned b0 = 0u, b1 = 1u; tf2x32(k0, k1, b0, b1);   // counter 1
    nk[0] = a0; nk[1] = a1;
    sk[0] = b0; sk[1] = b1;
}

// Partitionable-mode 32-bit random bits: bits[i] = x0 ^ x1 of threefry(key,(0,i))
__device__ __forceinline__ unsigned rb32(unsigned k0, unsigned k1, unsigned i) {
    unsigned x0 = 0u, x1 = i;
    tf2x32(k0, k1, x0, x1);
    return x0 ^ x1;
}

// ---------------- vector reduction helper ---------------------------------------
__device__ __forceinline__ void red_add_v4(float4* p, float x, float y, float z, float w) {
    asm volatile("red.global.add.v4.f32 [%0], {%1,%2,%3,%4};"
                 :: "l"(p), "f"(x), "f"(y), "f"(z), "f"(w) : "memory");
}

// ---------------- kernels -------------------------------------------------------

__global__ void k_zero() {
    int i = blockIdx.x * blockDim.x + threadIdx.x;
    if (i < N_) { g_order0[i] = 0.f; g_order1[i] = 0.f; }
    if (i < 256) g_hist[i] = 0u;
    if (i == 0) { g_prefix = 0u; g_rem = NCAND; g_selcount = 0; }
}

__global__ void k_initfst(const float4* __restrict__ emb4) {
    int i = blockIdx.x * blockDim.x + threadIdx.x;
    if (i >= N_ * 16) return;
    float4 b = emb4[i];
    g_fst[i] = make_float4(-b.x, -b.y, -b.z, -b.w);
}

// masks + masked edge values + rowsums of vals and v1
__global__ void k_mask(const int* __restrict__ rows, const float* __restrict__ vals,
                       unsigned a0, unsigned a1, unsigned b0, unsigned b1) {
    int e = blockIdx.x * blockDim.x + threadIdx.x;
    if (e >= E_) return;
    unsigned u1 = rb32(a0, a1, (unsigned)e);
    unsigned u2 = rb32(b0, b1, (unsigned)e);

    float v  = __ldg(vals + e);
    float v1 = (u1 >= 0x80000000u) ? v  : 0.f;   // uniform >= 0.5  (keep=0.5)
    float v2 = (u2 >= 0xC0000000u) ? v1 : 0.f;   // uniform >= 0.75 (keep=0.25)
    g_v1[e] = v1; g_v2[e] = v2;
    int r = __ldg(rows + e);
    atomicAdd(&g_order0[r], v);
    if (v1 != 0.f) atomicAdd(&g_order1[r], v1);
}

// scatter SpMM: 16 lanes per edge, float4 per lane.
// pass 1: vals=edge_vals, xin=embeds, xout=g_fst (no num)
// pass 2: vals=g_v1, xin=g_fst,  xout=g_emb1, num: order0 -> g_num1
// pass 3: vals=g_v2, xin=g_emb1, xout=g_emb2, num: g_num1 -> g_num2
__global__ void k_spmm(const int* __restrict__ rows, const int* __restrict__ cols,
                       const float* __restrict__ extvals, const float4* __restrict__ extx,
                       int pass) {
    unsigned t = blockIdx.x * blockDim.x + threadIdx.x;
    unsigned e = t >> 4;
    unsigned c = t & 15u;
    if (e >= E_) return;

    const float*  vals = (pass == 1) ? extvals : (pass == 2 ? g_v1 : g_v2);
    float v = __ldg(vals + e);
    if (v == 0.f) return;

    int col = __ldg(cols + e);
    int row = __ldg(rows + e);

    const float4* xin  = (pass == 1) ? extx : (pass == 2 ? g_fst : g_emb1);
    float4*       xout = (pass == 1) ? g_fst : (pass == 2 ? g_emb1 : g_emb2);

    float4 x = __ldg(xin + (size_t)col * 16 + c);
    red_add_v4(xout + (size_t)row * 16 + c, v * x.x, v * x.y, v * x.z, v * x.w);

    if (pass >= 2 && c == 0) {
        const float* numin  = (pass == 2) ? g_order0 : g_num1;
        float*       numout = (pass == 2) ? g_num1   : g_num2;
        atomicAdd(numout + row, v * __ldg(numin + col));
    }
}

// init for iteration 1: emb1 = -(1+order0)*fst ; num1 = -2*order0
__global__ void k_mid1() {
    int i = blockIdx.x * blockDim.x + threadIdx.x;
    if (i >= N_ * 16) return;
    int n = i >> 4, c = i & 15;
    float o = g_order0[n];
    float f = -(1.0f + o);
    float4 a = g_fst[i];
    g_emb1[i] = make_float4(f * a.x, f * a.y, f * a.z, f * a.w);
    if (c == 0) g_num1[n] = -2.0f * o;
}

// init for iteration 2: emb2 = -(1+order1)*emb1 ; num2 = -num1 - order1
__global__ void k_mid2() {
    int i = blockIdx.x * blockDim.x + threadIdx.x;
    if (i >= N_ * 16) return;
    int n = i >> 4, c = i & 15;
    float o = g_order1[n];
    float f = -(1.0f + o);
    float4 a = g_emb1[i];
    g_emb2[i] = make_float4(f * a.x, f * a.y, f * a.z, f * a.w);
    if (c == 0) g_num2[n] = -g_num1[n] - o;
}

// per-node score = cos(subgraph, embeds) + gumbel(kn), plus monotone sort key
__global__ void k_score(const float4* __restrict__ emb4, float* __restrict__ out,
                        unsigned n0, unsigned n1) {
    int n = blockIdx.x * blockDim.x + threadIdx.x;
    if (n >= N_) return;

    float ns  = g_order0[n] + g_num1[n] + g_num2[n];
    float inv = 1.0f / (ns + 1e-8f);

    const float4* f4  = g_fst  + (size_t)n * 16;
    const float4* e14 = g_emb1 + (size_t)n * 16;
    const float4* e24 = g_emb2 + (size_t)n * 16;
    const float4* b4  = emb4   + (size_t)n * 16;

    float sa = 0.f, sb = 0.f, dp = 0.f;
#pragma unroll
    for (int c = 0; c < 16; c++) {
        float4 a1 = f4[c], a2 = e14[c], a3 = e24[c], b = b4[c];
        float ax = (a1.x + a2.x + a3.x) * inv;
        float ay = (a1.y + a2.y + a3.y) * inv;
        float az = (a1.z + a2.z + a3.z) * inv;
        float aw = (a1.w + a2.w + a3.w) * inv;
        sa += ax * ax + ay * ay + az * az + aw * aw;
        sb += b.x * b.x + b.y * b.y + b.z * b.z + b.w * b.w;
        dp += ax * b.x + ay * b.y + az * b.z + aw * b.w;
    }
    float na = sqrtf(sa); if (na < 1e-12f) na = 1e-12f;
    float nb = sqrtf(sb); if (nb < 1e-12f) nb = 1e-12f;
    float score = dp / (na * nb);

    // Gumbel noise: u = uniform(kn)[n];  noise = -log(-log(u))
    unsigned bits = rb32(n0, n1, (unsigned)n);
    float u  = __uint_as_float(0x3F800000u | (bits >> 9)) - 1.0f;
    float nl = -logf(u);
    score += -logf(nl);

    out[n] = score;
    unsigned kk = __float_as_uint(score);
    kk = (kk & 0x80000000u) ? ~kk : (kk | 0x80000000u);   // monotone map
    g_keys[n] = kk;
}

// radix-select: histogram of 8-bit digit among elements matching current prefix
__global__ void k_hist(int pass) {
    int i = blockIdx.x * blockDim.x + threadIdx.x;
    if (i >= N_) return;
    int shift = 24 - 8 * pass;
    unsigned pmask = (pass == 0) ? 0u : (0xFFFFFFFFu << (shift + 8));
    unsigned k = g_keys[i];
    if ((k & pmask) == g_prefix)
        atomicAdd(&g_hist[(k >> shift) & 255u], 1u);
}

__global__ void k_scan(int pass) {
    if (threadIdx.x != 0) return;
    int shift = 24 - 8 * pass;
    int K = g_rem;
    unsigned c = 0;
    int d;
    for (d = 255; d >= 0; d--) {
        unsigned h = g_hist[d];
        if (c + h >= (unsigned)K) break;
        c += h;
    }
    if (d < 0) d = 0;
    g_prefix |= ((unsigned)d) << shift;
    g_rem = K - (int)c;
    for (int i = 0; i < 256; i++) g_hist[i] = 0u;
}

// collect everything >= exact 1024th key (ties included)
__global__ void k_select() {
    int i = blockIdx.x * blockDim.x + threadIdx.x;
    if (i >= N_) return;
    unsigned k = g_keys[i];
    if (k >= g_prefix) {
        int p = atomicAdd(&g_selcount, 1);
        if (p < CAP)
            g_cand[p] = (((unsigned long long)k) << 32) | (unsigned)(~(unsigned)i);
    }
}

// one-block bitonic sort (descending by key, ties ascending index), emit candidates
__global__ void k_sort(float* __restrict__ out) {
    __shared__ unsigned long long sm[CAP];
    int tid = threadIdx.x;
    int cnt = g_selcount; if (cnt > CAP) cnt = CAP;
    for (int s = 0; s < CAP / 1024; s++) {
        int i = tid + s * 1024;
        sm[i] = (i < cnt) ? g_cand[i] : 0ull;
    }
    __syncthreads();
    for (int k = 2; k <= CAP; k <<= 1) {
        for (int j = k >> 1; j > 0; j >>= 1) {
            for (int s = 0; s < CAP / 1024; s++) {
                int i = tid + s * 1024;
                int l = i ^ j;
                if (l > i) {
                    unsigned long long a = sm[i], b = sm[l];
                    bool up = ((i & k) == 0);
                    if ((a < b) == up) { sm[i] = b; sm[l] = a; }
                }
            }
            __syncthreads();
        }
    }
    unsigned idx = ~((unsigned)sm[tid]);
    out[N_ + tid] = (float)idx;
}

// ---------------- launch --------------------------------------------------------
extern "C" void kernel_launch(void* const* d_in, const int* in_sizes, int n_in,
                              void* d_out, int out_size) {
    const int*   rows   = (const int*)d_in[0];
    const int*   cols   = (const int*)d_in[1];
    const float* vals   = (const float*)d_in[2];
    const float* embeds = (const float*)d_in[3];
    float* out = (float*)d_out;

    // key chain (partitionable): key(42) -> (split) kd1 -> (split) kd2 -> (split) kn
    unsigned k0 = 0u, k1 = 42u, nk[2], kd1[2], kd2[2], kn[2];
    jax_split_part(k0, k1, nk, kd1); k0 = nk[0]; k1 = nk[1];
    jax_split_part(k0, k1, nk, kd2); k0 = nk[0]; k1 = nk[1];
    jax_split_part(k0, k1, nk, kn);

    const int B = 256;
    const int gN    = (N_ + B - 1) / B;
    const int gND   = (N_ * 16 + B - 1) / B;
    const int gE    = (E_ + B - 1) / B;
    const int gE16  = (int)(((long long)E_ * 16 + B - 1) / B);

    k_zero<<<gN, B>>>();
    k_initfst<<<gND, B>>>((const float4*)embeds);
    k_mask<<<gE, B>>>(rows, vals, kd1[0], kd1[1], kd2[0], kd2[1]);

    k_spmm<<<gE16, B>>>(rows, cols, vals, (const float4*)embeds, 1);
    k_mid1<<<gND, B>>>();
    k_spmm<<<gE16, B>>>(rows, cols, vals, (const float4*)embeds, 2);
    k_mid2<<<gND, B>>>();
    k_spmm<<<gE16, B>>>(rows, cols, vals, (const float4*)embeds, 3);

    k_score<<<gN, B>>>((const float4*)embeds, out, kn[0], kn[1]);

    for (int p = 0; p < 4; p++) {
        k_hist<<<gN, B>>>(p);
        k_scan<<<1, 32>>>(p);
    }
    k_select<<<gN, B>>>();
    k_sort<<<1, 1024>>>(out);
}

// round 3
// speedup vs baseline: 2.4735x; 2.4735x over previous
#include <cuda_runtime.h>
#include <cstdint>

#define N_ 100000
#define E_ 3200000
#define NCAND 1024
#define CAP 4096
#define SCAN_B 256
#define NBLK ((N_ + SCAN_B - 1) / SCAN_B)   // 391

// ---------------- device scratch (static, no runtime allocation) ----------------
__device__ float4 g_fst [N_*16];
__device__ float4 g_emb1[N_*16];
__device__ uint2  g_edge[E_];         // CSR records: (col|m1<<30|m12<<31, val bits)
__device__ unsigned char g_mask[E_];
__device__ float  g_order0[N_];
__device__ float  g_order1[N_];
__device__ float  g_num1[N_];
__device__ int    g_deg[N_];
__device__ int    g_rowptr[N_ + 1];
__device__ int    g_cursor[N_];
__device__ int    g_blocktot[NBLK];
__device__ int    g_blockoff[NBLK];
__device__ unsigned g_keys[N_];
__device__ unsigned g_hist[256];
__device__ unsigned g_prefix;
__device__ int g_rem;
__device__ int g_selcount;
__device__ unsigned long long g_cand[CAP];

// ---------------- Threefry-2x32 (20 rounds, 5 key injections) -------------------
#define TFR(a,b,r) { a += b; b = ((b << (r)) | (b >> (32-(r)))); b ^= a; }

__host__ __device__ __forceinline__ void tf2x32(unsigned k0, unsigned k1,
                                                unsigned& x0, unsigned& x1) {
    unsigned k2 = k0 ^ k1 ^ 0x1BD11BDAu;
    x0 += k0; x1 += k1;
    TFR(x0,x1,13) TFR(x0,x1,15) TFR(x0,x1,26) TFR(x0,x1,6)
    x0 += k1; x1 += k2 + 1u;
    TFR(x0,x1,17) TFR(x0,x1,29) TFR(x0,x1,16) TFR(x0,x1,24)
    x0 += k2; x1 += k0 + 2u;
    TFR(x0,x1,13) TFR(x0,x1,15) TFR(x0,x1,26) TFR(x0,x1,6)
    x0 += k0; x1 += k1 + 3u;
    TFR(x0,x1,17) TFR(x0,x1,29) TFR(x0,x1,16) TFR(x0,x1,24)
    x0 += k1; x1 += k2 + 4u;
    TFR(x0,x1,13) TFR(x0,x1,15) TFR(x0,x1,26) TFR(x0,x1,6)
    x0 += k2; x1 += k0 + 5u;
}

// Partitionable-mode split: split(key,2)[j] = threefry(key, (0, j))
static void jax_split_part(unsigned k0, unsigned k1, unsigned* nk, unsigned* sk) {
    unsigned a0 = 0u, a1 = 0u; tf2x32(k0, k1, a0, a1);
    unsigned b0 = 0u, b1 = 1u; tf2x32(k0, k1, b0, b1);
    nk[0] = a0; nk[1] = a1;
    sk[0] = b0; sk[1] = b1;
}

__device__ __forceinline__ unsigned rb32(unsigned k0, unsigned k1, unsigned i) {
    unsigned x0 = 0u, x1 = i;
    tf2x32(k0, k1, x0, x1);
    return x0 ^ x1;
}

// ---------------- kernels -------------------------------------------------------

__global__ void k_zero() {
    int i = blockIdx.x * blockDim.x + threadIdx.x;
    if (i < N_) { g_order0[i] = 0.f; g_order1[i] = 0.f; g_deg[i] = 0; }
    if (i < 256) g_hist[i] = 0u;
    if (i == 0) { g_prefix = 0u; g_rem = NCAND; g_selcount = 0; g_rowptr[N_] = E_; }
}

// masks (RNG), degree count, order rowsums
__global__ void k_count(const int* __restrict__ rows, const float* __restrict__ vals,
                        unsigned a0, unsigned a1, unsigned b0, unsigned b1) {
    int e = blockIdx.x * blockDim.x + threadIdx.x;
    if (e >= E_) return;
    unsigned u1 = rb32(a0, a1, (unsigned)e);
    unsigned u2 = rb32(b0, b1, (unsigned)e);
    int m1  = (u1 >= 0x80000000u) ? 1 : 0;          // keep prob 0.5
    int m12 = (m1 && u2 >= 0xC0000000u) ? 1 : 0;    // joint keep (0.5 * 0.25 path)
    g_mask[e] = (unsigned char)(m1 | (m12 << 1));
    float v = __ldg(vals + e);
    int r = __ldg(rows + e);
    atomicAdd(&g_deg[r], 1);
    atomicAdd(&g_order0[r], v);
    if (m1) atomicAdd(&g_order1[r], v);
}

// ---- prefix scan over degrees -> rowptr ----
__global__ void k_scanA() {
    __shared__ int s[SCAN_B];
    int i = blockIdx.x * SCAN_B + threadIdx.x;
    s[threadIdx.x] = (i < N_) ? g_deg[i] : 0;
    __syncthreads();
    for (int off = SCAN_B / 2; off > 0; off >>= 1) {
        if (threadIdx.x < off) s[threadIdx.x] += s[threadIdx.x + off];
        __syncthreads();
    }
    if (threadIdx.x == 0) g_blocktot[blockIdx.x] = s[0];
}

__global__ void k_scanB() {
    __shared__ int s[512];
    int t = threadIdx.x;
    int v0 = (t < NBLK) ? g_blocktot[t] : 0;
    s[t] = v0;
    __syncthreads();
    for (int off = 1; off < 512; off <<= 1) {
        int v = s[t];
        if (t >= off) v += s[t - off];
        __syncthreads();
        s[t] = v;
        __syncthreads();
    }
    if (t < NBLK) g_blockoff[t] = s[t] - v0;   // exclusive
}

__global__ void k_scanC() {
    __shared__ int s[SCAN_B];
    int i = blockIdx.x * SCAN_B + threadIdx.x;
    int d = (i < N_) ? g_deg[i] : 0;
    s[threadIdx.x] = d;
    __syncthreads();
    for (int off = 1; off < SCAN_B; off <<= 1) {
        int v = s[threadIdx.x];
        if (threadIdx.x >= off) v += s[threadIdx.x - off];
        __syncthreads();
        s[threadIdx.x] = v;
        __syncthreads();
    }
    if (i < N_) {
        int ex = g_blockoff[blockIdx.x] + s[threadIdx.x] - d;
        g_rowptr[i] = ex;
        g_cursor[i] = ex;
    }
}

// scatter edges into CSR slots
__global__ void k_fill(const int* __restrict__ rows, const int* __restrict__ cols,
                       const float* __restrict__ vals) {
    int e = blockIdx.x * blockDim.x + threadIdx.x;
    if (e >= E_) return;
    int r = __ldg(rows + e);
    int pos = atomicAdd(&g_cursor[r], 1);
    unsigned m = g_mask[e];
    unsigned colm = (unsigned)__ldg(cols + e) | ((m & 1u) << 30) | ((m >> 1) << 31);
    g_edge[pos] = make_uint2(colm, __float_as_uint(__ldg(vals + e)));
}

// ---- gather SpMM passes (16 lanes per row) ----
// PASS 1: xin=embeds,  out g_fst  = sum - embeds[r]
// PASS 2: xin=g_fst,   out g_emb1 = sum - (1+order0)*fst[r]; num1 = ns - 2*order0
// PASS 3: xin=g_emb1,  fused scoring epilogue (emb2/num2 kept in registers)
template<int PASS>
__global__ void k_pass(const float4* __restrict__ embeds, float* __restrict__ out,
                       unsigned n0, unsigned n1) {
    unsigned t = blockIdx.x * blockDim.x + threadIdx.x;
    int r = (int)(t >> 4);
    int c = (int)(t & 15u);
    if (r >= N_) return;

    const float4* xin  = (PASS == 1) ? embeds : (PASS == 2 ? g_fst : g_emb1);
    const float*  numin = (PASS == 2) ? g_order0 : g_num1;

    int beg = __ldg(&g_rowptr[r]);
    int end = __ldg(&g_rowptr[r + 1]);

    float4 acc = make_float4(0.f, 0.f, 0.f, 0.f);
    float ns = 0.f;

    for (int e = beg; e < end; ++e) {
        uint2 er = __ldg(&g_edge[e]);
        unsigned colm = er.x;
        if (PASS == 2 && !(colm & (1u << 30))) continue;
        if (PASS == 3 && !(colm & (1u << 31))) continue;
        unsigned col = colm & 0x00FFFFFFu;
        float v = __uint_as_float(er.y);
        float4 x = __ldg(&xin[(size_t)col * 16 + c]);
        acc.x += v * x.x; acc.y += v * x.y; acc.z += v * x.z; acc.w += v * x.w;
        if (PASS >= 2) ns += v * __ldg(&numin[col]);
    }

    size_t idx = (size_t)r * 16 + c;

    if (PASS == 1) {
        float4 b = __ldg(&embeds[idx]);
        g_fst[idx] = make_float4(acc.x - b.x, acc.y - b.y, acc.z - b.z, acc.w - b.w);
    } else if (PASS == 2) {
        float o = __ldg(&g_order0[r]);
        float f = 1.0f + o;
        float4 p = __ldg(&g_fst[idx]);
        g_emb1[idx] = make_float4(acc.x - f * p.x, acc.y - f * p.y,
                                  acc.z - f * p.z, acc.w - f * p.w);
        if (c == 0) g_num1[r] = ns - 2.0f * o;
    } else {
        // emb2 = acc - (1+order1)*emb1 ; num2 = ns - num1 - order1
        float o1 = __ldg(&g_order1[r]);
        float o0 = __ldg(&g_order0[r]);
        float n1v = __ldg(&g_num1[r]);
        float f = 1.0f + o1;
        float4 e1 = __ldg(&g_emb1[idx]);
        float4 p  = __ldg(&g_fst[idx]);
        float4 b  = __ldg(&embeds[idx]);
        float e2x = acc.x - f * e1.x, e2y = acc.y - f * e1.y;
        float e2z = acc.z - f * e1.z, e2w = acc.w - f * e1.w;
        float num2 = ns - n1v - o1;
        float num_sum = o0 + n1v + num2;
        float inv = 1.0f / (num_sum + 1e-8f);
        float ax = (p.x + e1.x + e2x) * inv;
        float ay = (p.y + e1.y + e2y) * inv;
        float az = (p.z + e1.z + e2z) * inv;
        float aw = (p.w + e1.w + e2w) * inv;
        float sa = ax * ax + ay * ay + az * az + aw * aw;
        float sb = b.x * b.x + b.y * b.y + b.z * b.z + b.w * b.w;
        float dp = ax * b.x + ay * b.y + az * b.z + aw * b.w;
        // reduce across the 16 lanes of this row
        for (int off = 8; off > 0; off >>= 1) {
            sa += __shfl_down_sync(0xFFFFFFFFu, sa, off, 16);
            sb += __shfl_down_sync(0xFFFFFFFFu, sb, off, 16);
            dp += __shfl_down_sync(0xFFFFFFFFu, dp, off, 16);
        }
        if (c == 0) {
            float na = sqrtf(sa); if (na < 1e-12f) na = 1e-12f;
            float nb = sqrtf(sb); if (nb < 1e-12f) nb = 1e-12f;
            float score = dp / (na * nb);
            unsigned bits = rb32(n0, n1, (unsigned)r);
            float u = __uint_as_float(0x3F800000u | (bits >> 9)) - 1.0f;
            score += -logf(-logf(u));
            out[r] = score;
            unsigned kk = __float_as_uint(score);
            kk = (kk & 0x80000000u) ? ~kk : (kk | 0x80000000u);
            g_keys[r] = kk;
        }
    }
}

// ---- radix-select top-1024 ----
__global__ void k_hist(int pass) {
    int i = blockIdx.x * blockDim.x + threadIdx.x;
    if (i >= N_) return;
    int shift = 24 - 8 * pass;
    unsigned pmask = (pass == 0) ? 0u : (0xFFFFFFFFu << (shift + 8));
    unsigned k = g_keys[i];
    if ((k & pmask) == g_prefix)
        atomicAdd(&g_hist[(k >> shift) & 255u], 1u);
}

__global__ void k_scan(int pass) {
    if (threadIdx.x != 0) return;
    int shift = 24 - 8 * pass;
    int K = g_rem;
    unsigned c = 0;
    int d;
    for (d = 255; d >= 0; d--) {
        unsigned h = g_hist[d];
        if (c + h >= (unsigned)K) break;
        c += h;
    }
    if (d < 0) d = 0;
    g_prefix |= ((unsigned)d) << shift;
    g_rem = K - (int)c;
    for (int i = 0; i < 256; i++) g_hist[i] = 0u;
}

__global__ void k_select() {
    int i = blockIdx.x * blockDim.x + threadIdx.x;
    if (i >= N_) return;
    unsigned k = g_keys[i];
    if (k >= g_prefix) {
        int p = atomicAdd(&g_selcount, 1);
        if (p < CAP)
            g_cand[p] = (((unsigned long long)k) << 32) | (unsigned)(~(unsigned)i);
    }
}

__global__ void k_sort(float* __restrict__ out) {
    __shared__ unsigned long long sm[CAP];
    int tid = threadIdx.x;
    int cnt = g_selcount; if (cnt > CAP) cnt = CAP;
    for (int s = 0; s < CAP / 1024; s++) {
        int i = tid + s * 1024;
        sm[i] = (i < cnt) ? g_cand[i] : 0ull;
    }
    __syncthreads();
    for (int k = 2; k <= CAP; k <<= 1) {
        for (int j = k >> 1; j > 0; j >>= 1) {
            for (int s = 0; s < CAP / 1024; s++) {
                int i = tid + s * 1024;
                int l = i ^ j;
                if (l > i) {
                    unsigned long long a = sm[i], b = sm[l];
                    bool up = ((i & k) == 0);
                    if ((a < b) == up) { sm[i] = b; sm[l] = a; }
                }
            }
            __syncthreads();
        }
    }
    unsigned idx = ~((unsigned)sm[tid]);
    out[N_ + tid] = (float)idx;
}

// ---------------- launch --------------------------------------------------------
extern "C" void kernel_launch(void* const* d_in, const int* in_sizes, int n_in,
                              void* d_out, int out_size) {
    const int*   rows   = (const int*)d_in[0];
    const int*   cols   = (const int*)d_in[1];
    const float* vals   = (const float*)d_in[2];
    const float* embeds = (const float*)d_in[3];
    float* out = (float*)d_out;

    // key chain (partitionable): key(42) -> (split) kd1 -> (split) kd2 -> (split) kn
    unsigned k0 = 0u, k1 = 42u, nk[2], kd1[2], kd2[2], kn[2];
    jax_split_part(k0, k1, nk, kd1); k0 = nk[0]; k1 = nk[1];
    jax_split_part(k0, k1, nk, kd2); k0 = nk[0]; k1 = nk[1];
    jax_split_part(k0, k1, nk, kn);

    const int B = 256;
    const int gN   = (N_ + B - 1) / B;
    const int gN16 = (N_ * 16 + B - 1) / B;
    const int gE   = (E_ + B - 1) / B;

    k_zero<<<gN, B>>>();
    k_count<<<gE, B>>>(rows, vals, kd1[0], kd1[1], kd2[0], kd2[1]);
    k_scanA<<<NBLK, SCAN_B>>>();
    k_scanB<<<1, 512>>>();
    k_scanC<<<NBLK, SCAN_B>>>();
    k_fill<<<gE, B>>>(rows, cols, vals);

    k_pass<1><<<gN16, B>>>((const float4*)embeds, out, kn[0], kn[1]);
    k_pass<2><<<gN16, B>>>((const float4*)embeds, out, kn[0], kn[1]);
    k_pass<3><<<gN16, B>>>((const float4*)embeds, out, kn[0], kn[1]);

    for (int p = 0; p < 4; p++) {
        k_hist<<<gN, B>>>(p);
        k_scan<<<1, 32>>>(p);
    }
    k_select<<<gN, B>>>();
    k_sort<<<1, 1024>>>(out);
}

// round 4
// speedup vs baseline: 2.6433x; 1.0686x over previous
#include <cuda_runtime.h>
#include <cstdint>

#define N_ 100000
#define E_ 3200000
#define NCAND 1024
#define CAP 4096
#define SCAN_B 256
#define NBLK ((N_ + SCAN_B - 1) / SCAN_B)   // 391

// ---------------- device scratch (static, no runtime allocation) ----------------
__device__ float2 g_fst [N_*32];
__device__ float2 g_emb1[N_*32];
__device__ uint2  g_edge[E_];          // CSR records: (col, val bits), segmented
__device__ float  g_order0[N_];
__device__ float  g_order1[N_];
__device__ float  g_num1[N_];
__device__ unsigned g_cnt[N_];         // packed: deg | cnt_m1<<10 | cnt_m12<<20
__device__ unsigned g_cursor[N_];      // packed per-class cursors
__device__ unsigned g_seg[N_];         // cnt_m12 | cnt_m1<<16
__device__ int    g_rowptr[N_ + 1];
__device__ int    g_blocktot[NBLK];
__device__ int    g_blockoff[NBLK];
__device__ unsigned g_keys[N_];
__device__ unsigned g_hist[256];
__device__ unsigned g_prefix;
__device__ int g_rem;
__device__ int g_ticket;
__device__ int g_selcount;
__device__ unsigned long long g_cand[CAP];

// ---------------- Threefry-2x32 (20 rounds, 5 key injections) -------------------
#define TFR(a,b,r) { a += b; b = ((b << (r)) | (b >> (32-(r)))); b ^= a; }

__host__ __device__ __forceinline__ void tf2x32(unsigned k0, unsigned k1,
                                                unsigned& x0, unsigned& x1) {
    unsigned k2 = k0 ^ k1 ^ 0x1BD11BDAu;
    x0 += k0; x1 += k1;
    TFR(x0,x1,13) TFR(x0,x1,15) TFR(x0,x1,26) TFR(x0,x1,6)
    x0 += k1; x1 += k2 + 1u;
    TFR(x0,x1,17) TFR(x0,x1,29) TFR(x0,x1,16) TFR(x0,x1,24)
    x0 += k2; x1 += k0 + 2u;
    TFR(x0,x1,13) TFR(x0,x1,15) TFR(x0,x1,26) TFR(x0,x1,6)
    x0 += k0; x1 += k1 + 3u;
    TFR(x0,x1,17) TFR(x0,x1,29) TFR(x0,x1,16) TFR(x0,x1,24)
    x0 += k1; x1 += k2 + 4u;
    TFR(x0,x1,13) TFR(x0,x1,15) TFR(x0,x1,26) TFR(x0,x1,6)
    x0 += k2; x1 += k0 + 5u;
}

static void jax_split_part(unsigned k0, unsigned k1, unsigned* nk, unsigned* sk) {
    unsigned a0 = 0u, a1 = 0u; tf2x32(k0, k1, a0, a1);
    unsigned b0 = 0u, b1 = 1u; tf2x32(k0, k1, b0, b1);
    nk[0] = a0; nk[1] = a1;
    sk[0] = b0; sk[1] = b1;
}

__device__ __forceinline__ unsigned rb32(unsigned k0, unsigned k1, unsigned i) {
    unsigned x0 = 0u, x1 = i;
    tf2x32(k0, k1, x0, x1);
    return x0 ^ x1;
}

// ---------------- kernels -------------------------------------------------------

__global__ void k_zero() {
    int i = blockIdx.x * blockDim.x + threadIdx.x;
    if (i < N_) { g_cnt[i] = 0u; g_cursor[i] = 0u; }
    if (i < 256) g_hist[i] = 0u;
    if (i == 0) {
        g_prefix = 0u; g_rem = NCAND; g_selcount = 0; g_ticket = 0;
        g_rowptr[N_] = E_;
    }
}

// RNG masks + packed per-row class counts (single atomic per edge)
__global__ void k_count(const int* __restrict__ rows,
                        unsigned a0, unsigned a1, unsigned b0, unsigned b1) {
    int e = blockIdx.x * blockDim.x + threadIdx.x;
    if (e >= E_) return;
    unsigned u1 = rb32(a0, a1, (unsigned)e);
    unsigned u2 = rb32(b0, b1, (unsigned)e);
    unsigned m1  = (u1 >= 0x80000000u) ? 1u : 0u;           // keep prob 0.5
    unsigned m12 = (m1 && u2 >= 0xC0000000u) ? 1u : 0u;     // joint keep
    int r = __ldg(rows + e);
    atomicAdd(&g_cnt[r], 1u + (m1 << 10) + (m12 << 20));
}

// ---- prefix scan over degrees -> rowptr; also emit segment counts ----
__global__ void k_scanA() {
    __shared__ int s[SCAN_B];
    int i = blockIdx.x * SCAN_B + threadIdx.x;
    s[threadIdx.x] = (i < N_) ? (int)(g_cnt[i] & 1023u) : 0;
    __syncthreads();
    for (int off = SCAN_B / 2; off > 0; off >>= 1) {
        if (threadIdx.x < off) s[threadIdx.x] += s[threadIdx.x + off];
        __syncthreads();
    }
    if (threadIdx.x == 0) g_blocktot[blockIdx.x] = s[0];
}

__global__ void k_scanB() {
    __shared__ int s[512];
    int t = threadIdx.x;
    int v0 = (t < NBLK) ? g_blocktot[t] : 0;
    s[t] = v0;
    __syncthreads();
    for (int off = 1; off < 512; off <<= 1) {
        int v = s[t];
        if (t >= off) v += s[t - off];
        __syncthreads();
        s[t] = v;
        __syncthreads();
    }
    if (t < NBLK) g_blockoff[t] = s[t] - v0;   // exclusive
}

__global__ void k_scanC() {
    __shared__ int s[SCAN_B];
    int i = blockIdx.x * SCAN_B + threadIdx.x;
    unsigned pc = (i < N_) ? g_cnt[i] : 0u;
    int d = (int)(pc & 1023u);
    s[threadIdx.x] = d;
    __syncthreads();
    for (int off = 1; off < SCAN_B; off <<= 1) {
        int v = s[threadIdx.x];
        if (threadIdx.x >= off) v += s[threadIdx.x - off];
        __syncthreads();
        s[threadIdx.x] = v;
        __syncthreads();
    }
    if (i < N_) {
        g_rowptr[i] = g_blockoff[blockIdx.x] + s[threadIdx.x] - d;
        unsigned cnt1  = (pc >> 10) & 1023u;
        unsigned cnt12 = (pc >> 20) & 1023u;
        g_seg[i] = cnt12 | (cnt1 << 16);
    }
}

// scatter edges into segmented CSR slots: [m12][m1-only][dropped]
__global__ void k_fill(const int* __restrict__ rows, const int* __restrict__ cols,
                       const float* __restrict__ vals,
                       unsigned a0, unsigned a1, unsigned b0, unsigned b1) {
    int e = blockIdx.x * blockDim.x + threadIdx.x;
    if (e >= E_) return;
    unsigned u1 = rb32(a0, a1, (unsigned)e);
    unsigned u2 = rb32(b0, b1, (unsigned)e);
    unsigned m1  = (u1 >= 0x80000000u) ? 1u : 0u;
    unsigned m12 = (m1 && u2 >= 0xC0000000u) ? 1u : 0u;
    int cls = m12 ? 0 : (m1 ? 1 : 2);

    int r = __ldg(rows + e);
    unsigned old = atomicAdd(&g_cursor[r], 1u << (10 * cls));
    unsigned within = (old >> (10 * cls)) & ((cls == 2) ? 0xFFFu : 1023u);
    unsigned seg = __ldg(&g_seg[r]);
    unsigned segbase = (cls == 0) ? 0u : ((cls == 1) ? (seg & 0xFFFFu) : (seg >> 16));
    int pos = __ldg(&g_rowptr[r]) + (int)(segbase + within);
    g_edge[pos] = make_uint2((unsigned)__ldg(cols + e), __float_as_uint(__ldg(vals + e)));
}

// ---- gather SpMM passes: 1 warp per row, float2 per lane ----
// PASS 1: xin=embeds, out fst = sum - embeds[r]; order0 = sum v
// PASS 2: xin=fst (first cnt1), out emb1 = sum - (1+order0)*fst; num1, order1
// PASS 3: xin=emb1 (first cnt12), fused scoring epilogue
template<int PASS>
__global__ void k_pass(const float2* __restrict__ embeds, float* __restrict__ out,
                       unsigned n0, unsigned n1) {
    unsigned t = blockIdx.x * blockDim.x + threadIdx.x;
    int w = (int)(t >> 5);
    int c = (int)(t & 31u);
    if (w >= N_) return;

    const float2* xin = (PASS == 1) ? embeds : (PASS == 2 ? g_fst : g_emb1);
    const float* numin = (PASS == 2) ? g_order0 : g_num1;

    int beg = __ldg(&g_rowptr[w]);
    unsigned seg = __ldg(&g_seg[w]);
    int cnt = (PASS == 1) ? (__ldg(&g_rowptr[w + 1]) - beg)
            : (PASS == 2) ? (int)(seg >> 16)
                          : (int)(seg & 0xFFFFu);

    float ax = 0.f, ay = 0.f;
    float ns = 0.f, o1acc = 0.f;

    #pragma unroll 4
    for (int e = beg; e < beg + cnt; ++e) {
        uint2 er = __ldg(&g_edge[e]);
        float v = __uint_as_float(er.y);
        float2 x = __ldg(&xin[(size_t)er.x * 32 + c]);
        ax += v * x.x; ay += v * x.y;
        if (PASS == 1) ns += v;
        else           ns += v * __ldg(&numin[er.x]);
        if (PASS == 2) o1acc += v;
    }

    size_t idx = (size_t)w * 32 + c;

    if (PASS == 1) {
        float2 b = __ldg(&embeds[idx]);
        g_fst[idx] = make_float2(ax - b.x, ay - b.y);
        if (c == 0) g_order0[w] = ns;
    } else if (PASS == 2) {
        float o = __ldg(&g_order0[w]);
        float f = 1.0f + o;
        float2 p = __ldg(&g_fst[idx]);
        g_emb1[idx] = make_float2(ax - f * p.x, ay - f * p.y);
        if (c == 0) { g_num1[w] = ns - 2.0f * o; g_order1[w] = o1acc; }
    } else {
        float o1  = __ldg(&g_order1[w]);
        float o0  = __ldg(&g_order0[w]);
        float n1v = __ldg(&g_num1[w]);
        float f = 1.0f + o1;
        float2 e1 = __ldg(&g_emb1[idx]);
        float2 p  = __ldg(&g_fst[idx]);
        float2 b  = __ldg(&embeds[idx]);
        float e2x = ax - f * e1.x, e2y = ay - f * e1.y;
        float num2 = ns - n1v - o1;
        float inv = 1.0f / (o0 + n1v + num2 + 1e-8f);
        float sx = (p.x + e1.x + e2x) * inv;
        float sy = (p.y + e1.y + e2y) * inv;
        float sa = sx * sx + sy * sy;
        float sb = b.x * b.x + b.y * b.y;
        float dp = sx * b.x + sy * b.y;
        for (int off = 16; off > 0; off >>= 1) {
            sa += __shfl_down_sync(0xFFFFFFFFu, sa, off);
            sb += __shfl_down_sync(0xFFFFFFFFu, sb, off);
            dp += __shfl_down_sync(0xFFFFFFFFu, dp, off);
        }
        if (c == 0) {
            float na = sqrtf(sa); if (na < 1e-12f) na = 1e-12f;
            float nb = sqrtf(sb); if (nb < 1e-12f) nb = 1e-12f;
            float score = dp / (na * nb);
            unsigned bits = rb32(n0, n1, (unsigned)w);
            float u = __uint_as_float(0x3F800000u | (bits >> 9)) - 1.0f;
            score += -logf(-logf(u));
            out[w] = score;
            unsigned kk = __float_as_uint(score);
            kk = (kk & 0x80000000u) ? ~kk : (kk | 0x80000000u);
            g_keys[w] = kk;
        }
    }
}

// ---- fused radix histogram + scan (last-block ticket) ----
__global__ void k_histscan(int pass) {
    __shared__ unsigned sh[256];
    __shared__ int s_last;
    int tid = threadIdx.x;
    if (tid < 256) sh[tid] = 0u;
    __syncthreads();

    int i = blockIdx.x * blockDim.x + tid;
    int shift = 24 - 8 * pass;
    unsigned pmask = (pass == 0) ? 0u : (0xFFFFFFFFu << (shift + 8));
    unsigned pref = g_prefix;
    if (i < N_) {
        unsigned k = g_keys[i];
        if ((k & pmask) == pref)
            atomicAdd(&sh[(k >> shift) & 255u], 1u);
    }
    __syncthreads();
    if (tid < 256 && sh[tid]) atomicAdd(&g_hist[tid], sh[tid]);
    __threadfence();
    __syncthreads();
    if (tid == 0)
        s_last = (atomicAdd(&g_ticket, 1) == (int)gridDim.x - 1) ? 1 : 0;
    __syncthreads();
    if (!s_last) return;

    if (tid == 0) {
        int K = g_rem;
        unsigned c = 0;
        int d;
        for (d = 255; d >= 0; d--) {
            unsigned h = *((volatile unsigned*)&g_hist[d]);
            if (c + h >= (unsigned)K) break;
            c += h;
        }
        if (d < 0) d = 0;
        g_prefix = pref | (((unsigned)d) << shift);
        g_rem = K - (int)c;
        g_ticket = 0;
    }
    __syncthreads();
    if (tid < 256) g_hist[tid] = 0u;
}

// collect everything >= 24-bit prefix threshold (>=1024, <CAP candidates)
__global__ void k_select() {
    int i = blockIdx.x * blockDim.x + threadIdx.x;
    if (i >= N_) return;
    unsigned k = g_keys[i];
    if (k >= g_prefix) {
        int p = atomicAdd(&g_selcount, 1);
        if (p < CAP)
            g_cand[p] = (((unsigned long long)k) << 32) | (unsigned)(~(unsigned)i);
    }
}

__global__ void k_sort(float* __restrict__ out) {
    __shared__ unsigned long long sm[CAP];
    int tid = threadIdx.x;
    int cnt = g_selcount; if (cnt > CAP) cnt = CAP;
    for (int s = 0; s < CAP / 1024; s++) {
        int i = tid + s * 1024;
        sm[i] = (i < cnt) ? g_cand[i] : 0ull;
    }
    __syncthreads();
    for (int k = 2; k <= CAP; k <<= 1) {
        for (int j = k >> 1; j > 0; j >>= 1) {
            for (int s = 0; s < CAP / 1024; s++) {
                int i = tid + s * 1024;
                int l = i ^ j;
                if (l > i) {
                    unsigned long long a = sm[i], b = sm[l];
                    bool up = ((i & k) == 0);
                    if ((a < b) == up) { sm[i] = b; sm[l] = a; }
                }
            }
            __syncthreads();
        }
    }
    unsigned idx = ~((unsigned)sm[tid]);
    out[N_ + tid] = (float)idx;
}

// ---------------- launch --------------------------------------------------------
extern "C" void kernel_launch(void* const* d_in, const int* in_sizes, int n_in,
                              void* d_out, int out_size) {
    const int*   rows   = (const int*)d_in[0];
    const int*   cols   = (const int*)d_in[1];
    const float* vals   = (const float*)d_in[2];
    const float* embeds = (const float*)d_in[3];
    float* out = (float*)d_out;

    // key chain (partitionable): key(42) -> (split) kd1 -> (split) kd2 -> (split) kn
    unsigned k0 = 0u, k1 = 42u, nk[2], kd1[2], kd2[2], kn[2];
    jax_split_part(k0, k1, nk, kd1); k0 = nk[0]; k1 = nk[1];
    jax_split_part(k0, k1, nk, kd2); k0 = nk[0]; k1 = nk[1];
    jax_split_part(k0, k1, nk, kn);

    const int B = 256;
    const int gN   = (N_ + B - 1) / B;
    const int gN32 = (N_ * 32 + B - 1) / B;
    const int gE   = (E_ + B - 1) / B;
    const int gH   = (N_ + 511) / 512;

    k_zero<<<gN, B>>>();
    k_count<<<gE, B>>>(rows, kd1[0], kd1[1], kd2[0], kd2[1]);
    k_scanA<<<NBLK, SCAN_B>>>();
    k_scanB<<<1, 512>>>();
    k_scanC<<<NBLK, SCAN_B>>>();
    k_fill<<<gE, B>>>(rows, cols, vals, kd1[0], kd1[1], kd2[0], kd2[1]);

    k_pass<1><<<gN32, B>>>((const float2*)embeds, out, kn[0], kn[1]);
    k_pass<2><<<gN32, B>>>((const float2*)embeds, out, kn[0], kn[1]);
    k_pass<3><<<gN32, B>>>((const float2*)embeds, out, kn[0], kn[1]);

    for (int p = 0; p < 3; p++)
        k_histscan<<<gH, 512>>>(p);
    k_select<<<gN, B>>>();
    k_sort<<<1, 1024>>>(out);
}